// round 3
// baseline (speedup 1.0000x reference)
#include <cuda_runtime.h>
#include <cuda_fp16.h>

#define NN 50000
#define EE 800000
#define HH 128
#define GG 500
#define FC1 64
#define EPSBN 1e-5f
#define AGG_NB 6250      /* 50000/8 */
#define MID_NB 125       /* 6250/50 */

// ---------------- device scratch (static, no allocation) ----------------
__device__ __align__(16) unsigned g_h16u[NN * (HH / 2)];  // fp16 message matrix
__device__ float g_agg[NN * HH];                          // aggregated (pre-BN) fp32
__device__ int   g_cnt[NN];
__device__ int   g_fill[NN];
__device__ int   g_ptr[NN + 1];
__device__ float g_dis[NN];
__device__ int   g_csr_src[EE];
__device__ float g_csr_w[EE];
__device__ float g_ps1[AGG_NB * HH];
__device__ float g_pq1[AGG_NB * HH];
__device__ float g_ps2[MID_NB * HH];
__device__ float g_pq2[MID_NB * HH];
__device__ float g_bn_a[HH];
__device__ float g_bn_b[HH];
__device__ int   g_goff[GG + 1];
__device__ float g_pooled[GG * HH];
__device__ float g_z[GG * FC1];
__device__ float g_fc_a[FC1];
__device__ float g_fc_b[FC1];
__device__ int   g_is64;

// ---------------- helpers ----------------
__device__ __forceinline__ int ld_idx(const void* p, long long i, int is64) {
    return is64 ? (int)(((const long long*)p)[i]) : ((const int*)p)[i];
}

__device__ __forceinline__ unsigned f2tf32(float v) {
    unsigned o;
    asm("cvt.rna.tf32.f32 %0, %1;" : "=r"(o) : "f"(v));
    return o;
}

// ---------------- preprocessing ----------------
// zero counters; block 0 additionally detects int64-vs-int32 index dtype
__global__ void k_zero(const void* eidx) {
    int i = blockIdx.x * blockDim.x + threadIdx.x;
    if (i < NN) { g_cnt[i] = 0; g_fill[i] = 0; }
    if (blockIdx.x == 0) {
        __shared__ int any;
        if (threadIdx.x == 0) any = 0;
        __syncthreads();
        if (((const int*)eidx)[2 * threadIdx.x + 1] != 0) atomicOr(&any, 1);
        __syncthreads();
        if (threadIdx.x == 0) g_is64 = any ? 0 : 1;
    }
}

__global__ void k_count(const void* eidx) {
    int e = blockIdx.x * blockDim.x + threadIdx.x;
    if (e >= EE) return;
    int is64 = g_is64;
    int d = ld_idx(eidx, (long long)EE + e, is64);
    atomicAdd(&g_cnt[d], 1);
}

// batch sorted: graph offsets via boundary compare (one coalesced pass)
__global__ void k_gbounds(const void* batch) {
    int i = blockIdx.x * blockDim.x + threadIdx.x;
    if (i >= NN) return;
    int is64 = g_is64;
    int b = ld_idx(batch, i, is64);
    int bn = (i + 1 < NN) ? ld_idx(batch, i + 1, is64) : GG;
    if (i == 0)
        for (int g = 0; g <= b; g++) g_goff[g] = 0;
    for (int g = b + 1; g <= bn; g++) g_goff[g] = i + 1;
}

// single-block exclusive scan over node counts; also writes dis = rsqrt(deg)
__global__ void k_scan() {
    const int CH = 49;
    __shared__ int sm[1024];
    int t = threadIdx.x;
    int base = t * CH;
    int len = NN - base;
    if (len < 0) len = 0;
    if (len > CH) len = CH;
    int s = 0;
    for (int i = 0; i < len; i++) s += g_cnt[base + i];
    sm[t] = s;
    __syncthreads();
    for (int off = 1; off < 1024; off <<= 1) {
        int v = (t >= off) ? sm[t - off] : 0;
        __syncthreads();
        sm[t] += v;
        __syncthreads();
    }
    int run = sm[t] - s;
    for (int i = 0; i < len; i++) {
        int c = g_cnt[base + i];
        g_ptr[base + i] = run;
        g_dis[base + i] = rsqrtf((float)(c + 1));
        run += c;
    }
    if (base < NN && base + CH >= NN) g_ptr[NN] = run;
}

__global__ void k_fill(const void* eidx) {
    int e = blockIdx.x * blockDim.x + threadIdx.x;
    if (e >= EE) return;
    int is64 = g_is64;
    int s = ld_idx(eidx, e, is64);
    int d = ld_idx(eidx, (long long)EE + e, is64);
    int pos = atomicAdd(&g_fill[d], 1);
    int slot = g_ptr[d] + pos;
    g_csr_src[slot] = s;
    g_csr_w[slot] = g_dis[s] * g_dis[d];
}

// ---------------- 3xTF32 tensor-core GEMM ----------------
// g_h16u[N,128](fp16) = f(X)[N,128] @ W[128,128], f = id or BN+ReLU.
// Block: 64 x 128, 256 threads, warps 2(M) x 4(N); warp tile 32x32 (2x4 m16n8k8).
// Numerics: x = xh + xl (tf32 split); acc += xh*wh + xh*wl + xl*wh.
#define XS_STRIDE 132
#define WS_STRIDE 136
#define GEMM_SMEM ((2 * 64 * XS_STRIDE + 2 * 128 * WS_STRIDE) * 4)

template <bool BN>
__global__ void __launch_bounds__(256) k_gemm_tc(const float* __restrict__ X,
                                                 const float* __restrict__ W) {
    extern __shared__ float smem[];
    float* Xh = smem;
    float* Xl = Xh + 64 * XS_STRIDE;
    float* Wh = Xl + 64 * XS_STRIDE;
    float* Wl = Wh + 128 * WS_STRIDE;
    int tid = threadIdx.x;
    int row0 = blockIdx.x * 64;

    // X tile 64x128, fused BN+ReLU, hi/lo tf32 split
#pragma unroll
    for (int i = 0; i < 8; i++) {
        int q = i * 256 + tid;
        int r = q >> 5;
        int c = (q & 31) * 4;
        int gr = row0 + r;
        float4 v = make_float4(0.f, 0.f, 0.f, 0.f);
        if (gr < NN) v = *(const float4*)(X + (size_t)gr * 128 + c);
        if (BN) {
            v.x = fmaxf(g_bn_a[c + 0] * v.x + g_bn_b[c + 0], 0.f);
            v.y = fmaxf(g_bn_a[c + 1] * v.y + g_bn_b[c + 1], 0.f);
            v.z = fmaxf(g_bn_a[c + 2] * v.z + g_bn_b[c + 2], 0.f);
            v.w = fmaxf(g_bn_a[c + 3] * v.w + g_bn_b[c + 3], 0.f);
        }
        float* dh = Xh + r * XS_STRIDE + c;
        float* dl = Xl + r * XS_STRIDE + c;
        unsigned hx = f2tf32(v.x), hy = f2tf32(v.y), hz = f2tf32(v.z), hw = f2tf32(v.w);
        dh[0] = __uint_as_float(hx); dh[1] = __uint_as_float(hy);
        dh[2] = __uint_as_float(hz); dh[3] = __uint_as_float(hw);
        dl[0] = __uint_as_float(f2tf32(v.x - __uint_as_float(hx)));
        dl[1] = __uint_as_float(f2tf32(v.y - __uint_as_float(hy)));
        dl[2] = __uint_as_float(f2tf32(v.z - __uint_as_float(hz)));
        dl[3] = __uint_as_float(f2tf32(v.w - __uint_as_float(hw)));
    }
    // W tile 128x128, hi/lo
#pragma unroll
    for (int i = 0; i < 16; i++) {
        int q = i * 256 + tid;
        int r = q >> 5;
        int c = (q & 31) * 4;
        float4 v = *(const float4*)(W + (size_t)r * 128 + c);
        float* dh = Wh + r * WS_STRIDE + c;
        float* dl = Wl + r * WS_STRIDE + c;
        unsigned hx = f2tf32(v.x), hy = f2tf32(v.y), hz = f2tf32(v.z), hw = f2tf32(v.w);
        dh[0] = __uint_as_float(hx); dh[1] = __uint_as_float(hy);
        dh[2] = __uint_as_float(hz); dh[3] = __uint_as_float(hw);
        dl[0] = __uint_as_float(f2tf32(v.x - __uint_as_float(hx)));
        dl[1] = __uint_as_float(f2tf32(v.y - __uint_as_float(hy)));
        dl[2] = __uint_as_float(f2tf32(v.z - __uint_as_float(hz)));
        dl[3] = __uint_as_float(f2tf32(v.w - __uint_as_float(hw)));
    }
    __syncthreads();

    int wid = tid >> 5;
    int lane = tid & 31;
    int mwid = wid >> 2;
    int nwid = wid & 3;
    int g = lane >> 2;
    int tg = lane & 3;

    float acc[2][4][4];
#pragma unroll
    for (int mi = 0; mi < 2; mi++)
#pragma unroll
        for (int ni = 0; ni < 4; ni++)
#pragma unroll
            for (int j = 0; j < 4; j++) acc[mi][ni][j] = 0.f;

#define MMA(A0, A1, A2, A3, B0, B1, C)                                        \
    asm volatile(                                                             \
        "mma.sync.aligned.m16n8k8.row.col.f32.tf32.tf32.f32 "                 \
        "{%0,%1,%2,%3}, {%4,%5,%6,%7}, {%8,%9}, {%0,%1,%2,%3};"               \
        : "+f"(C[0]), "+f"(C[1]), "+f"(C[2]), "+f"(C[3])                      \
        : "r"(A0), "r"(A1), "r"(A2), "r"(A3), "r"(B0), "r"(B1))

#pragma unroll
    for (int k0 = 0; k0 < 128; k0 += 8) {
        unsigned ah[2][4], al[2][4];
#pragma unroll
        for (int mi = 0; mi < 2; mi++) {
            int rb = mwid * 32 + mi * 16;
            int o0 = (rb + g) * XS_STRIDE + k0 + tg;
            int o1 = (rb + g + 8) * XS_STRIDE + k0 + tg;
            ah[mi][0] = __float_as_uint(Xh[o0]);
            ah[mi][1] = __float_as_uint(Xh[o1]);
            ah[mi][2] = __float_as_uint(Xh[o0 + 4]);
            ah[mi][3] = __float_as_uint(Xh[o1 + 4]);
            al[mi][0] = __float_as_uint(Xl[o0]);
            al[mi][1] = __float_as_uint(Xl[o1]);
            al[mi][2] = __float_as_uint(Xl[o0 + 4]);
            al[mi][3] = __float_as_uint(Xl[o1 + 4]);
        }
        unsigned bh[4][2], bl[4][2];
#pragma unroll
        for (int ni = 0; ni < 4; ni++) {
            int cb = nwid * 32 + ni * 8;
            int o0 = (k0 + tg) * WS_STRIDE + cb + g;
            int o1 = (k0 + tg + 4) * WS_STRIDE + cb + g;
            bh[ni][0] = __float_as_uint(Wh[o0]);
            bh[ni][1] = __float_as_uint(Wh[o1]);
            bl[ni][0] = __float_as_uint(Wl[o0]);
            bl[ni][1] = __float_as_uint(Wl[o1]);
        }
#pragma unroll
        for (int mi = 0; mi < 2; mi++)
#pragma unroll
            for (int ni = 0; ni < 4; ni++) {
                MMA(ah[mi][0], ah[mi][1], ah[mi][2], ah[mi][3],
                    bh[ni][0], bh[ni][1], acc[mi][ni]);
                MMA(ah[mi][0], ah[mi][1], ah[mi][2], ah[mi][3],
                    bl[ni][0], bl[ni][1], acc[mi][ni]);
                MMA(al[mi][0], al[mi][1], al[mi][2], al[mi][3],
                    bh[ni][0], bh[ni][1], acc[mi][ni]);
            }
    }

    // epilogue: fp16 pairs
#pragma unroll
    for (int mi = 0; mi < 2; mi++) {
#pragma unroll
        for (int ni = 0; ni < 4; ni++) {
            int col = nwid * 32 + ni * 8 + tg * 2;
            int r1 = row0 + mwid * 32 + mi * 16 + g;
            int r2 = r1 + 8;
            if (r1 < NN) {
                __half2 h = __floats2half2_rn(acc[mi][ni][0], acc[mi][ni][1]);
                g_h16u[(size_t)r1 * 64 + (col >> 1)] = *(unsigned*)&h;
            }
            if (r2 < NN) {
                __half2 h = __floats2half2_rn(acc[mi][ni][2], acc[mi][ni][3]);
                g_h16u[(size_t)r2 * 64 + (col >> 1)] = *(unsigned*)&h;
            }
        }
    }
#undef MMA
}

// ---------------- aggregation (fp16 gather) + fused BN partial stats --------
__global__ void __launch_bounds__(256) k_agg(const float* __restrict__ bias) {
    __shared__ float ps[8][HH];
    __shared__ float pq[8][HH];
    int w = threadIdx.x >> 5;
    int lane = threadIdx.x & 31;
    int d = blockIdx.x * 8 + w;   // NN = 6250*8 exact

    const uint2* Hv = (const uint2*)g_h16u;
    float sd = g_dis[d];
    float ws = sd * sd;
    uint2 u = Hv[(size_t)d * 32 + lane];
    float2 f0 = __half22float2(*(__half2*)&u.x);
    float2 f1 = __half22float2(*(__half2*)&u.y);
    float4 acc = make_float4(f0.x * ws, f0.y * ws, f1.x * ws, f1.y * ws);

    int beg = g_ptr[d], end = g_ptr[d + 1];
    int j = beg;
    for (; j + 4 <= end; j += 4) {
        int s0 = g_csr_src[j + 0], s1 = g_csr_src[j + 1];
        int s2 = g_csr_src[j + 2], s3 = g_csr_src[j + 3];
        float w0 = g_csr_w[j + 0], w1 = g_csr_w[j + 1];
        float w2 = g_csr_w[j + 2], w3 = g_csr_w[j + 3];
        uint2 u0 = Hv[(size_t)s0 * 32 + lane];
        uint2 u1 = Hv[(size_t)s1 * 32 + lane];
        uint2 u2 = Hv[(size_t)s2 * 32 + lane];
        uint2 u3 = Hv[(size_t)s3 * 32 + lane];
        float2 a, b;
        a = __half22float2(*(__half2*)&u0.x); b = __half22float2(*(__half2*)&u0.y);
        acc.x += a.x * w0; acc.y += a.y * w0; acc.z += b.x * w0; acc.w += b.y * w0;
        a = __half22float2(*(__half2*)&u1.x); b = __half22float2(*(__half2*)&u1.y);
        acc.x += a.x * w1; acc.y += a.y * w1; acc.z += b.x * w1; acc.w += b.y * w1;
        a = __half22float2(*(__half2*)&u2.x); b = __half22float2(*(__half2*)&u2.y);
        acc.x += a.x * w2; acc.y += a.y * w2; acc.z += b.x * w2; acc.w += b.y * w2;
        a = __half22float2(*(__half2*)&u3.x); b = __half22float2(*(__half2*)&u3.y);
        acc.x += a.x * w3; acc.y += a.y * w3; acc.z += b.x * w3; acc.w += b.y * w3;
    }
    for (; j < end; j++) {
        int s = g_csr_src[j];
        float wj = g_csr_w[j];
        uint2 us = Hv[(size_t)s * 32 + lane];
        float2 a = __half22float2(*(__half2*)&us.x);
        float2 b = __half22float2(*(__half2*)&us.y);
        acc.x += a.x * wj; acc.y += a.y * wj; acc.z += b.x * wj; acc.w += b.y * wj;
    }
    float4 b4 = ((const float4*)bias)[lane];
    acc.x += b4.x; acc.y += b4.y; acc.z += b4.z; acc.w += b4.w;
    ((float4*)(g_agg + (size_t)d * HH))[lane] = acc;

    // BN partial stats (deterministic fixed-order 8-way sum)
    int c0 = 4 * lane;
    ps[w][c0 + 0] = acc.x; ps[w][c0 + 1] = acc.y;
    ps[w][c0 + 2] = acc.z; ps[w][c0 + 3] = acc.w;
    pq[w][c0 + 0] = acc.x * acc.x; pq[w][c0 + 1] = acc.y * acc.y;
    pq[w][c0 + 2] = acc.z * acc.z; pq[w][c0 + 3] = acc.w * acc.w;
    __syncthreads();
    int t = threadIdx.x;
    if (t < HH) {
        float s = 0.f;
#pragma unroll
        for (int i = 0; i < 8; i++) s += ps[i][t];
        g_ps1[blockIdx.x * HH + t] = s;
    } else {
        int c = t - HH;
        float s = 0.f;
#pragma unroll
        for (int i = 0; i < 8; i++) s += pq[i][c];
        g_pq1[blockIdx.x * HH + c] = s;
    }
}

// ---------------- BN stats finish (two tiny stages) ----------------
__global__ void k_stats_mid() {
    int c = threadIdx.x;
    float s = 0.f, q = 0.f;
    for (int r = blockIdx.x; r < AGG_NB; r += MID_NB) {
        s += g_ps1[r * HH + c];
        q += g_pq1[r * HH + c];
    }
    g_ps2[blockIdx.x * HH + c] = s;
    g_pq2[blockIdx.x * HH + c] = q;
}

__global__ void k_stats_final(const float* __restrict__ gam, const float* __restrict__ bet) {
    int c = threadIdx.x;
    float s = 0.f, q = 0.f;
    for (int b = 0; b < MID_NB; b++) {
        s += g_ps2[b * HH + c];
        q += g_pq2[b * HH + c];
    }
    float m = s / (float)NN;
    float var = q / (float)NN - m * m;
    float a = gam[c] * rsqrtf(var + EPSBN);
    g_bn_a[c] = a;
    g_bn_b[c] = bet[c] - m * a;
}

// ---------------- pooling (layer-3 BN+ReLU fused) ----------------
__global__ void k_pool() {
    int gI = blockIdx.x;
    int c = threadIdx.x;
    int beg = g_goff[gI], end = g_goff[gI + 1];
    float a = g_bn_a[c], b = g_bn_b[c];
    float acc = 0.f;
    for (int r = beg; r < end; r++) {
        float v = g_agg[(size_t)r * HH + c];
        acc += fmaxf(a * v + b, 0.f);
    }
    float cnt = (float)(end - beg);
    g_pooled[gI * HH + c] = acc / fmaxf(cnt, 1.f);
}

// ---------------- FC head ----------------
__global__ void k_fc1(const float* __restrict__ Wf, const float* __restrict__ bf) {
    __shared__ float psm[128];
    int gI = blockIdx.x;
    int c = threadIdx.x;  // 64 threads
    psm[c] = g_pooled[gI * HH + c];
    psm[c + 64] = g_pooled[gI * HH + c + 64];
    __syncthreads();
    float s = bf[c];
#pragma unroll 8
    for (int k = 0; k < 128; k++) s += psm[k] * Wf[k * FC1 + c];
    g_z[gI * FC1 + c] = s;
}

__global__ void k_fcstats(const float* __restrict__ gam, const float* __restrict__ bet) {
    int c = threadIdx.x;
    float s = 0.f, q = 0.f;
#pragma unroll 4
    for (int r = 0; r < GG; r++) {
        float v = g_z[r * FC1 + c];
        s += v;
        q += v * v;
    }
    float m = s / (float)GG;
    float var = q / (float)GG - m * m;
    float a = gam[c] * rsqrtf(var + EPSBN);
    g_fc_a[c] = a;
    g_fc_b[c] = bet[c] - m * a;
}

__global__ void k_fc2(const float* __restrict__ W2f, const float* __restrict__ b2f,
                      float* __restrict__ out) {
    int gI = blockIdx.x * blockDim.x + threadIdx.x;
    if (gI >= GG) return;
    float s = b2f[0];
#pragma unroll 8
    for (int c = 0; c < FC1; c++) {
        float v = g_z[gI * FC1 + c];
        v = fmaxf(g_fc_a[c] * v + g_fc_b[c], 0.f);
        s += v * W2f[c];
    }
    out[gI] = s;
}

// ---------------- launch ----------------
extern "C" void kernel_launch(void* const* d_in, const int* in_sizes, int n_in,
                              void* d_out, int out_size) {
    const float* x    = (const float*)d_in[0];
    const void*  eidx = d_in[1];
    const void*  batc = d_in[2];
    const float* W1 = (const float*)d_in[3];
    const float* b1 = (const float*)d_in[4];
    const float* g1 = (const float*)d_in[5];
    const float* be1 = (const float*)d_in[6];
    const float* W2 = (const float*)d_in[7];
    const float* b2 = (const float*)d_in[8];
    const float* g2 = (const float*)d_in[9];
    const float* be2 = (const float*)d_in[10];
    const float* W3 = (const float*)d_in[11];
    const float* b3 = (const float*)d_in[12];
    const float* g3 = (const float*)d_in[13];
    const float* be3 = (const float*)d_in[14];
    const float* fcW1 = (const float*)d_in[15];
    const float* fcb1 = (const float*)d_in[16];
    const float* fcg1 = (const float*)d_in[17];
    const float* fcbe1 = (const float*)d_in[18];
    const float* fcW2 = (const float*)d_in[19];
    const float* fcb2 = (const float*)d_in[20];
    float* out = (float*)d_out;

    float* pagg = nullptr;
    cudaGetSymbolAddress((void**)&pagg, g_agg);

    const int TB = 256;
    const int gemm_blocks = (NN + 63) / 64;
    static int smem_set = 0;
    if (!smem_set) {
        cudaFuncSetAttribute(k_gemm_tc<false>,
                             cudaFuncAttributeMaxDynamicSharedMemorySize, GEMM_SMEM);
        cudaFuncSetAttribute(k_gemm_tc<true>,
                             cudaFuncAttributeMaxDynamicSharedMemorySize, GEMM_SMEM);
        smem_set = 1;
    }

    k_zero<<<(NN + TB - 1) / TB, TB>>>(eidx);
    k_count<<<(EE + TB - 1) / TB, TB>>>(eidx);
    k_gbounds<<<(NN + TB - 1) / TB, TB>>>(batc);
    k_scan<<<1, 1024>>>();
    k_fill<<<(EE + TB - 1) / TB, TB>>>(eidx);

    // layer 1
    k_gemm_tc<false><<<gemm_blocks, TB, GEMM_SMEM>>>(x, W1);
    k_agg<<<AGG_NB, TB>>>(b1);
    k_stats_mid<<<MID_NB, HH>>>();
    k_stats_final<<<1, HH>>>(g1, be1);
    // layer 2
    k_gemm_tc<true><<<gemm_blocks, TB, GEMM_SMEM>>>(pagg, W2);
    k_agg<<<AGG_NB, TB>>>(b2);
    k_stats_mid<<<MID_NB, HH>>>();
    k_stats_final<<<1, HH>>>(g2, be2);
    // layer 3
    k_gemm_tc<true><<<gemm_blocks, TB, GEMM_SMEM>>>(pagg, W3);
    k_agg<<<AGG_NB, TB>>>(b3);
    k_stats_mid<<<MID_NB, HH>>>();
    k_stats_final<<<1, HH>>>(g3, be3);

    // pool + head
    k_pool<<<GG, HH>>>();
    k_fc1<<<GG, FC1>>>(fcW1, fcb1);
    k_fcstats<<<1, FC1>>>(fcg1, fcbe1);
    k_fc2<<<(GG + TB - 1) / TB, TB>>>(fcW2, fcb2, out);
}

// round 4
// speedup vs baseline: 1.2467x; 1.2467x over previous
#include <cuda_runtime.h>
#include <cuda_fp16.h>

#define NN 50000
#define EE 800000
#define HH 128
#define GG 500
#define FC1 64
#define EPSBN 1e-5f
#define AGG_NB 6250      /* 50000/8 */
#define MID_NB 125       /* 6250/50 */
#define SCAN_TB 256
#define SCAN_NB 196      /* 196*256 = 50176 >= NN */

// ---------------- device scratch (static, no allocation) ----------------
__device__ __align__(16) unsigned g_h16u[NN * (HH / 2)];  // fp16 message matrix
__device__ float g_agg[NN * HH];                          // aggregated (pre-BN) fp32
__device__ int   g_cnt[NN];
__device__ int   g_fill[NN];
__device__ int   g_ptr[NN + 1];
__device__ float g_dis[NN];
__device__ int   g_csr_src[EE];
__device__ float g_csr_w[EE];
__device__ int   g_bsum[SCAN_NB];
__device__ int   g_boff[SCAN_NB];
__device__ float g_ps1[AGG_NB * HH];
__device__ float g_pq1[AGG_NB * HH];
__device__ float g_ps2[MID_NB * HH];
__device__ float g_pq2[MID_NB * HH];
__device__ float g_bn_a[HH];
__device__ float g_bn_b[HH];
__device__ int   g_goff[GG + 1];
__device__ float g_pooled[GG * HH];
__device__ float g_z[GG * FC1];
__device__ float g_fc_a[FC1];
__device__ float g_fc_b[FC1];
__device__ int   g_is64;

// ---------------- helpers ----------------
__device__ __forceinline__ int ld_idx(const void* p, long long i, int is64) {
    return is64 ? (int)(((const long long*)p)[i]) : ((const int*)p)[i];
}

__device__ __forceinline__ unsigned f2tf32(float v) {
    unsigned o;
    asm("cvt.rna.tf32.f32 %0, %1;" : "=r"(o) : "f"(v));
    return o;
}

// ---------------- preprocessing ----------------
__global__ void k_zero(const void* eidx) {
    int i = blockIdx.x * blockDim.x + threadIdx.x;
    if (i < NN) { g_cnt[i] = 0; g_fill[i] = 0; }
    if (blockIdx.x == 0) {
        __shared__ int any;
        if (threadIdx.x == 0) any = 0;
        __syncthreads();
        if (((const int*)eidx)[2 * threadIdx.x + 1] != 0) atomicOr(&any, 1);
        __syncthreads();
        if (threadIdx.x == 0) g_is64 = any ? 0 : 1;
    }
}

__global__ void k_count(const void* eidx) {
    int e = blockIdx.x * blockDim.x + threadIdx.x;
    if (e >= EE) return;
    int is64 = g_is64;
    int d = ld_idx(eidx, (long long)EE + e, is64);
    atomicAdd(&g_cnt[d], 1);
}

// batch sorted: graph offsets via boundary compare (one coalesced pass)
__global__ void k_gbounds(const void* batch) {
    int i = blockIdx.x * blockDim.x + threadIdx.x;
    if (i >= NN) return;
    int is64 = g_is64;
    int b = ld_idx(batch, i, is64);
    int bn = (i + 1 < NN) ? ld_idx(batch, i + 1, is64) : GG;
    if (i == 0)
        for (int g = 0; g <= b; g++) g_goff[g] = 0;
    for (int g = b + 1; g <= bn; g++) g_goff[g] = i + 1;
}

// ---- multi-block exclusive scan of g_cnt -> g_ptr (3 tiny stages) ----
__global__ void k_blocksum() {
    __shared__ int sm[SCAN_TB];
    int i = blockIdx.x * SCAN_TB + threadIdx.x;
    int c = (i < NN) ? g_cnt[i] : 0;
    sm[threadIdx.x] = c;
    __syncthreads();
    for (int off = SCAN_TB / 2; off > 0; off >>= 1) {
        if (threadIdx.x < off) sm[threadIdx.x] += sm[threadIdx.x + off];
        __syncthreads();
    }
    if (threadIdx.x == 0) g_bsum[blockIdx.x] = sm[0];
}

__global__ void k_scanb() {
    __shared__ int sm[SCAN_TB];
    int t = threadIdx.x;
    int v = (t < SCAN_NB) ? g_bsum[t] : 0;
    sm[t] = v;
    __syncthreads();
    for (int off = 1; off < SCAN_TB; off <<= 1) {
        int u = (t >= off) ? sm[t - off] : 0;
        __syncthreads();
        sm[t] += u;
        __syncthreads();
    }
    if (t < SCAN_NB) g_boff[t] = sm[t] - v;  // exclusive
}

__global__ void k_ptrfill() {
    __shared__ int sm[SCAN_TB];
    int t = threadIdx.x;
    int i = blockIdx.x * SCAN_TB + t;
    int c = (i < NN) ? g_cnt[i] : 0;
    sm[t] = c;
    __syncthreads();
    for (int off = 1; off < SCAN_TB; off <<= 1) {
        int u = (t >= off) ? sm[t - off] : 0;
        __syncthreads();
        sm[t] += u;
        __syncthreads();
    }
    int ex = sm[t] - c + g_boff[blockIdx.x];
    if (i < NN) {
        g_ptr[i] = ex;
        g_dis[i] = rsqrtf((float)(c + 1));
        if (i == NN - 1) g_ptr[NN] = ex + c;
    }
}

__global__ void k_fill(const void* eidx) {
    int e = blockIdx.x * blockDim.x + threadIdx.x;
    if (e >= EE) return;
    int is64 = g_is64;
    int s = ld_idx(eidx, e, is64);
    int d = ld_idx(eidx, (long long)EE + e, is64);
    int pos = atomicAdd(&g_fill[d], 1);
    int slot = g_ptr[d] + pos;
    g_csr_src[slot] = s;
    g_csr_w[slot] = g_dis[s] * g_dis[d];
}

// ---------------- 3xTF32 tensor-core GEMM (fp32 smem, on-the-fly split) -----
// g_h16u[N,128](fp16) = f(X)[N,128] @ W[128,128], f = id or BN+ReLU.
// Block 64x128, 256 thr, warps 2(M)x4(N); warp tile 32x32 (2x4 m16n8k8).
// Numerics: per element x = xh + xl (tf32 split from registers);
// acc += xh*wh + xh*wl + xl*wh  (error ~2^-22, ~fp32).
#define XS_STRIDE 132
#define WS_STRIDE 136
#define GEMM_SMEM ((64 * XS_STRIDE + 128 * WS_STRIDE) * 4)

template <bool BN>
__global__ void __launch_bounds__(256) k_gemm_tc(const float* __restrict__ X,
                                                 const float* __restrict__ W) {
    extern __shared__ float smem[];
    float* Xs = smem;                    // [64][XS_STRIDE] fp32
    float* Ws = smem + 64 * XS_STRIDE;   // [128][WS_STRIDE] fp32
    int tid = threadIdx.x;
    int row0 = blockIdx.x * 64;

    // X tile 64x128 fp32 (fused BN+ReLU)
#pragma unroll
    for (int i = 0; i < 8; i++) {
        int q = i * 256 + tid;
        int r = q >> 5;
        int c = (q & 31) * 4;
        int gr = row0 + r;
        float4 v = make_float4(0.f, 0.f, 0.f, 0.f);
        if (gr < NN) v = *(const float4*)(X + (size_t)gr * 128 + c);
        if (BN) {
            v.x = fmaxf(g_bn_a[c + 0] * v.x + g_bn_b[c + 0], 0.f);
            v.y = fmaxf(g_bn_a[c + 1] * v.y + g_bn_b[c + 1], 0.f);
            v.z = fmaxf(g_bn_a[c + 2] * v.z + g_bn_b[c + 2], 0.f);
            v.w = fmaxf(g_bn_a[c + 3] * v.w + g_bn_b[c + 3], 0.f);
        }
        *(float4*)(Xs + r * XS_STRIDE + c) = v;
    }
    // W tile 128x128 fp32
#pragma unroll
    for (int i = 0; i < 16; i++) {
        int q = i * 256 + tid;
        int r = q >> 5;
        int c = (q & 31) * 4;
        *(float4*)(Ws + r * WS_STRIDE + c) = *(const float4*)(W + (size_t)r * 128 + c);
    }
    __syncthreads();

    int wid = tid >> 5;
    int lane = tid & 31;
    int mwid = wid >> 2;
    int nwid = wid & 3;
    int g = lane >> 2;
    int tg = lane & 3;

    float acc[2][4][4];
#pragma unroll
    for (int mi = 0; mi < 2; mi++)
#pragma unroll
        for (int ni = 0; ni < 4; ni++)
#pragma unroll
            for (int j = 0; j < 4; j++) acc[mi][ni][j] = 0.f;

#define SPLIT(V, HI, LO)                                 \
    do {                                                 \
        HI = f2tf32(V);                                  \
        LO = f2tf32((V) - __uint_as_float(HI));          \
    } while (0)

#define MMA(A0, A1, A2, A3, B0, B1, C)                                        \
    asm volatile(                                                             \
        "mma.sync.aligned.m16n8k8.row.col.f32.tf32.tf32.f32 "                 \
        "{%0,%1,%2,%3}, {%4,%5,%6,%7}, {%8,%9}, {%0,%1,%2,%3};"               \
        : "+f"(C[0]), "+f"(C[1]), "+f"(C[2]), "+f"(C[3])                      \
        : "r"(A0), "r"(A1), "r"(A2), "r"(A3), "r"(B0), "r"(B1))

#pragma unroll
    for (int k0 = 0; k0 < 128; k0 += 8) {
        unsigned ah[2][4], al[2][4];
#pragma unroll
        for (int mi = 0; mi < 2; mi++) {
            int rb = mwid * 32 + mi * 16;
            int o0 = (rb + g) * XS_STRIDE + k0 + tg;
            int o1 = (rb + g + 8) * XS_STRIDE + k0 + tg;
            float v0 = Xs[o0], v1 = Xs[o1], v2 = Xs[o0 + 4], v3 = Xs[o1 + 4];
            SPLIT(v0, ah[mi][0], al[mi][0]);
            SPLIT(v1, ah[mi][1], al[mi][1]);
            SPLIT(v2, ah[mi][2], al[mi][2]);
            SPLIT(v3, ah[mi][3], al[mi][3]);
        }
        unsigned bh[4][2], bl[4][2];
#pragma unroll
        for (int ni = 0; ni < 4; ni++) {
            int cb = nwid * 32 + ni * 8;
            int o0 = (k0 + tg) * WS_STRIDE + cb + g;
            int o1 = (k0 + tg + 4) * WS_STRIDE + cb + g;
            float v0 = Ws[o0], v1 = Ws[o1];
            SPLIT(v0, bh[ni][0], bl[ni][0]);
            SPLIT(v1, bh[ni][1], bl[ni][1]);
        }
#pragma unroll
        for (int mi = 0; mi < 2; mi++)
#pragma unroll
            for (int ni = 0; ni < 4; ni++) {
                MMA(ah[mi][0], ah[mi][1], ah[mi][2], ah[mi][3],
                    bh[ni][0], bh[ni][1], acc[mi][ni]);
                MMA(ah[mi][0], ah[mi][1], ah[mi][2], ah[mi][3],
                    bl[ni][0], bl[ni][1], acc[mi][ni]);
                MMA(al[mi][0], al[mi][1], al[mi][2], al[mi][3],
                    bh[ni][0], bh[ni][1], acc[mi][ni]);
            }
    }

    // epilogue: fp16 pairs
#pragma unroll
    for (int mi = 0; mi < 2; mi++) {
#pragma unroll
        for (int ni = 0; ni < 4; ni++) {
            int col = nwid * 32 + ni * 8 + tg * 2;
            int r1 = row0 + mwid * 32 + mi * 16 + g;
            int r2 = r1 + 8;
            if (r1 < NN) {
                __half2 h = __floats2half2_rn(acc[mi][ni][0], acc[mi][ni][1]);
                g_h16u[(size_t)r1 * 64 + (col >> 1)] = *(unsigned*)&h;
            }
            if (r2 < NN) {
                __half2 h = __floats2half2_rn(acc[mi][ni][2], acc[mi][ni][3]);
                g_h16u[(size_t)r2 * 64 + (col >> 1)] = *(unsigned*)&h;
            }
        }
    }
#undef MMA
#undef SPLIT
}

// ---------------- aggregation (fp16 gather) + fused BN partial stats --------
__global__ void __launch_bounds__(256) k_agg(const float* __restrict__ bias) {
    __shared__ float ps[8][HH];
    __shared__ float pq[8][HH];
    int w = threadIdx.x >> 5;
    int lane = threadIdx.x & 31;
    int d = blockIdx.x * 8 + w;   // NN = 6250*8 exact

    const uint2* Hv = (const uint2*)g_h16u;
    float sd = g_dis[d];
    float ws = sd * sd;
    uint2 u = Hv[(size_t)d * 32 + lane];
    float2 f0 = __half22float2(*(__half2*)&u.x);
    float2 f1 = __half22float2(*(__half2*)&u.y);
    float4 acc = make_float4(f0.x * ws, f0.y * ws, f1.x * ws, f1.y * ws);

    int beg = g_ptr[d], end = g_ptr[d + 1];
    int j = beg;
    for (; j + 4 <= end; j += 4) {
        int s0 = g_csr_src[j + 0], s1 = g_csr_src[j + 1];
        int s2 = g_csr_src[j + 2], s3 = g_csr_src[j + 3];
        float w0 = g_csr_w[j + 0], w1 = g_csr_w[j + 1];
        float w2 = g_csr_w[j + 2], w3 = g_csr_w[j + 3];
        uint2 u0 = Hv[(size_t)s0 * 32 + lane];
        uint2 u1 = Hv[(size_t)s1 * 32 + lane];
        uint2 u2 = Hv[(size_t)s2 * 32 + lane];
        uint2 u3 = Hv[(size_t)s3 * 32 + lane];
        float2 a, b;
        a = __half22float2(*(__half2*)&u0.x); b = __half22float2(*(__half2*)&u0.y);
        acc.x += a.x * w0; acc.y += a.y * w0; acc.z += b.x * w0; acc.w += b.y * w0;
        a = __half22float2(*(__half2*)&u1.x); b = __half22float2(*(__half2*)&u1.y);
        acc.x += a.x * w1; acc.y += a.y * w1; acc.z += b.x * w1; acc.w += b.y * w1;
        a = __half22float2(*(__half2*)&u2.x); b = __half22float2(*(__half2*)&u2.y);
        acc.x += a.x * w2; acc.y += a.y * w2; acc.z += b.x * w2; acc.w += b.y * w2;
        a = __half22float2(*(__half2*)&u3.x); b = __half22float2(*(__half2*)&u3.y);
        acc.x += a.x * w3; acc.y += a.y * w3; acc.z += b.x * w3; acc.w += b.y * w3;
    }
    for (; j < end; j++) {
        int s = g_csr_src[j];
        float wj = g_csr_w[j];
        uint2 us = Hv[(size_t)s * 32 + lane];
        float2 a = __half22float2(*(__half2*)&us.x);
        float2 b = __half22float2(*(__half2*)&us.y);
        acc.x += a.x * wj; acc.y += a.y * wj; acc.z += b.x * wj; acc.w += b.y * wj;
    }
    float4 b4 = ((const float4*)bias)[lane];
    acc.x += b4.x; acc.y += b4.y; acc.z += b4.z; acc.w += b4.w;
    ((float4*)(g_agg + (size_t)d * HH))[lane] = acc;

    // BN partial stats (deterministic fixed-order 8-way sum)
    int c0 = 4 * lane;
    ps[w][c0 + 0] = acc.x; ps[w][c0 + 1] = acc.y;
    ps[w][c0 + 2] = acc.z; ps[w][c0 + 3] = acc.w;
    pq[w][c0 + 0] = acc.x * acc.x; pq[w][c0 + 1] = acc.y * acc.y;
    pq[w][c0 + 2] = acc.z * acc.z; pq[w][c0 + 3] = acc.w * acc.w;
    __syncthreads();
    int t = threadIdx.x;
    if (t < HH) {
        float s = 0.f;
#pragma unroll
        for (int i = 0; i < 8; i++) s += ps[i][t];
        g_ps1[blockIdx.x * HH + t] = s;
    } else {
        int c = t - HH;
        float s = 0.f;
#pragma unroll
        for (int i = 0; i < 8; i++) s += pq[i][c];
        g_pq1[blockIdx.x * HH + c] = s;
    }
}

// ---------------- BN stats finish ----------------
__global__ void k_stats_mid() {
    int c = threadIdx.x;
    float s = 0.f, q = 0.f;
    for (int r = blockIdx.x; r < AGG_NB; r += MID_NB) {
        s += g_ps1[r * HH + c];
        q += g_pq1[r * HH + c];
    }
    g_ps2[blockIdx.x * HH + c] = s;
    g_pq2[blockIdx.x * HH + c] = q;
}

__global__ void k_stats_final(const float* __restrict__ gam, const float* __restrict__ bet) {
    int c = threadIdx.x;
    float s = 0.f, q = 0.f;
    for (int b = 0; b < MID_NB; b++) {
        s += g_ps2[b * HH + c];
        q += g_pq2[b * HH + c];
    }
    float m = s / (float)NN;
    float var = q / (float)NN - m * m;
    float a = gam[c] * rsqrtf(var + EPSBN);
    g_bn_a[c] = a;
    g_bn_b[c] = bet[c] - m * a;
}

// ---------------- pooling (layer-3 BN+ReLU fused) ----------------
__global__ void k_pool() {
    int gI = blockIdx.x;
    int c = threadIdx.x;
    int beg = g_goff[gI], end = g_goff[gI + 1];
    float a = g_bn_a[c], b = g_bn_b[c];
    float acc = 0.f;
    for (int r = beg; r < end; r++) {
        float v = g_agg[(size_t)r * HH + c];
        acc += fmaxf(a * v + b, 0.f);
    }
    float cnt = (float)(end - beg);
    g_pooled[gI * HH + c] = acc / fmaxf(cnt, 1.f);
}

// ---------------- FC head ----------------
__global__ void k_fc1(const float* __restrict__ Wf, const float* __restrict__ bf) {
    __shared__ float psm[128];
    int gI = blockIdx.x;
    int c = threadIdx.x;  // 64 threads
    psm[c] = g_pooled[gI * HH + c];
    psm[c + 64] = g_pooled[gI * HH + c + 64];
    __syncthreads();
    float s = bf[c];
#pragma unroll 8
    for (int k = 0; k < 128; k++) s += psm[k] * Wf[k * FC1 + c];
    g_z[gI * FC1 + c] = s;
}

__global__ void k_fcstats(const float* __restrict__ gam, const float* __restrict__ bet) {
    int c = threadIdx.x;
    float s = 0.f, q = 0.f;
#pragma unroll 4
    for (int r = 0; r < GG; r++) {
        float v = g_z[r * FC1 + c];
        s += v;
        q += v * v;
    }
    float m = s / (float)GG;
    float var = q / (float)GG - m * m;
    float a = gam[c] * rsqrtf(var + EPSBN);
    g_fc_a[c] = a;
    g_fc_b[c] = bet[c] - m * a;
}

__global__ void k_fc2(const float* __restrict__ W2f, const float* __restrict__ b2f,
                      float* __restrict__ out) {
    int gI = blockIdx.x * blockDim.x + threadIdx.x;
    if (gI >= GG) return;
    float s = b2f[0];
#pragma unroll 8
    for (int c = 0; c < FC1; c++) {
        float v = g_z[gI * FC1 + c];
        v = fmaxf(g_fc_a[c] * v + g_fc_b[c], 0.f);
        s += v * W2f[c];
    }
    out[gI] = s;
}

// ---------------- launch ----------------
extern "C" void kernel_launch(void* const* d_in, const int* in_sizes, int n_in,
                              void* d_out, int out_size) {
    const float* x    = (const float*)d_in[0];
    const void*  eidx = d_in[1];
    const void*  batc = d_in[2];
    const float* W1 = (const float*)d_in[3];
    const float* b1 = (const float*)d_in[4];
    const float* g1 = (const float*)d_in[5];
    const float* be1 = (const float*)d_in[6];
    const float* W2 = (const float*)d_in[7];
    const float* b2 = (const float*)d_in[8];
    const float* g2 = (const float*)d_in[9];
    const float* be2 = (const float*)d_in[10];
    const float* W3 = (const float*)d_in[11];
    const float* b3 = (const float*)d_in[12];
    const float* g3 = (const float*)d_in[13];
    const float* be3 = (const float*)d_in[14];
    const float* fcW1 = (const float*)d_in[15];
    const float* fcb1 = (const float*)d_in[16];
    const float* fcg1 = (const float*)d_in[17];
    const float* fcbe1 = (const float*)d_in[18];
    const float* fcW2 = (const float*)d_in[19];
    const float* fcb2 = (const float*)d_in[20];
    float* out = (float*)d_out;

    float* pagg = nullptr;
    cudaGetSymbolAddress((void**)&pagg, g_agg);

    const int TB = 256;
    const int gemm_blocks = (NN + 63) / 64;
    static int smem_set = 0;
    if (!smem_set) {
        cudaFuncSetAttribute(k_gemm_tc<false>,
                             cudaFuncAttributeMaxDynamicSharedMemorySize, GEMM_SMEM);
        cudaFuncSetAttribute(k_gemm_tc<true>,
                             cudaFuncAttributeMaxDynamicSharedMemorySize, GEMM_SMEM);
        smem_set = 1;
    }

    k_zero<<<(NN + TB - 1) / TB, TB>>>(eidx);
    k_count<<<(EE + TB - 1) / TB, TB>>>(eidx);
    k_gbounds<<<(NN + TB - 1) / TB, TB>>>(batc);
    k_blocksum<<<SCAN_NB, SCAN_TB>>>();
    k_scanb<<<1, SCAN_TB>>>();
    k_ptrfill<<<SCAN_NB, SCAN_TB>>>();
    k_fill<<<(EE + TB - 1) / TB, TB>>>(eidx);

    // layer 1
    k_gemm_tc<false><<<gemm_blocks, TB, GEMM_SMEM>>>(x, W1);
    k_agg<<<AGG_NB, TB>>>(b1);
    k_stats_mid<<<MID_NB, HH>>>();
    k_stats_final<<<1, HH>>>(g1, be1);
    // layer 2
    k_gemm_tc<true><<<gemm_blocks, TB, GEMM_SMEM>>>(pagg, W2);
    k_agg<<<AGG_NB, TB>>>(b2);
    k_stats_mid<<<MID_NB, HH>>>();
    k_stats_final<<<1, HH>>>(g2, be2);
    // layer 3
    k_gemm_tc<true><<<gemm_blocks, TB, GEMM_SMEM>>>(pagg, W3);
    k_agg<<<AGG_NB, TB>>>(b3);
    k_stats_mid<<<MID_NB, HH>>>();
    k_stats_final<<<1, HH>>>(g3, be3);

    // pool + head
    k_pool<<<GG, HH>>>();
    k_fc1<<<GG, FC1>>>(fcW1, fcb1);
    k_fcstats<<<1, FC1>>>(fcg1, fcbe1);
    k_fc2<<<(GG + TB - 1) / TB, TB>>>(fcW2, fcb2, out);
}

// round 5
// speedup vs baseline: 1.2774x; 1.0246x over previous
#include <cuda_runtime.h>
#include <cuda_fp16.h>

#define NN 50000
#define EE 800000
#define HH 128
#define GG 500
#define FC1 64
#define EPSBN 1e-5f
#define AGG_NB 6250      /* 50000/8 */
#define STAT_NB 128
#define SCAN_TB 256
#define SCAN_NB 196      /* 196*256 = 50176 >= NN */

// ---------------- device scratch (static, no allocation) ----------------
__device__ __align__(16) unsigned g_h16u[NN * (HH / 2)];  // fp16 message matrix
__device__ float g_agg[NN * HH];                          // aggregated (pre-BN) fp32
__device__ int   g_cnt[NN];
__device__ int   g_fill[NN];
__device__ int   g_ptr[NN + 1];
__device__ float g_dis[NN];
__device__ int   g_csr_src[EE];
__device__ float g_csr_w[EE];
__device__ int   g_bsum[SCAN_NB];
__device__ int   g_boff[SCAN_NB];
__device__ float g_ps1[AGG_NB * HH];
__device__ float g_pq1[AGG_NB * HH];
__device__ float g_mids[STAT_NB * HH];
__device__ float g_midq[STAT_NB * HH];
__device__ float g_bn_a[HH];
__device__ float g_bn_b[HH];
__device__ int   g_goff[GG + 1];
__device__ float g_z[GG * FC1];
__device__ float g_wh[3][HH * HH];   // tf32 hi parts of W1..W3
__device__ float g_wl[3][HH * HH];   // tf32 lo parts
__device__ int   g_tick;             // scanall ticket
__device__ int   g_flag;             // scanall release flag
__device__ int   g_tick2[3];         // stats tickets (per layer)
__device__ int   g_is64;

// ---------------- helpers ----------------
__device__ __forceinline__ int ld_idx(const void* p, long long i, int is64) {
    return is64 ? (int)(((const long long*)p)[i]) : ((const int*)p)[i];
}

__device__ __forceinline__ unsigned f2tf32(float v) {
    unsigned o;
    asm("cvt.rna.tf32.f32 %0, %1;" : "=r"(o) : "f"(v));
    return o;
}

// ---------------- pre1: zero + counters + dtype detect + W presplit --------
__global__ void k_pre1(const void* eidx, const float* W1, const float* W2,
                       const float* W3) {
    int i = blockIdx.x * blockDim.x + threadIdx.x;
    if (i < NN) { g_cnt[i] = 0; g_fill[i] = 0; }
    if (i == 0) {
        g_tick = 0; g_flag = 0;
        g_tick2[0] = 0; g_tick2[1] = 0; g_tick2[2] = 0;
    }
    if (blockIdx.x == 0) {
        __shared__ int any;
        if (threadIdx.x == 0) any = 0;
        __syncthreads();
        if (((const int*)eidx)[2 * threadIdx.x + 1] != 0) atomicOr(&any, 1);
        __syncthreads();
        if (threadIdx.x == 0) g_is64 = any ? 0 : 1;
    }
    // W tf32 hi/lo presplit: 3 * 16384 elements
    if (i < 3 * HH * HH) {
        int k = i / (HH * HH);
        int j = i - k * (HH * HH);
        float w = (k == 0) ? W1[j] : (k == 1) ? W2[j] : W3[j];
        unsigned hi = f2tf32(w);
        g_wh[k][j] = __uint_as_float(hi);
        g_wl[k][j] = __uint_as_float(f2tf32(w - __uint_as_float(hi)));
    }
}

// ---------------- count (edge histogram) + graph bounds ----------------
__global__ void k_count(const void* eidx, const void* batch) {
    int e = blockIdx.x * blockDim.x + threadIdx.x;
    int is64 = g_is64;
    if (e < EE) {
        int d = ld_idx(eidx, (long long)EE + e, is64);
        atomicAdd(&g_cnt[d], 1);
    }
    if (e < NN) {
        int b = ld_idx(batch, e, is64);
        int bn = (e + 1 < NN) ? ld_idx(batch, e + 1, is64) : GG;
        if (e == 0)
            for (int g = 0; g <= b; g++) g_goff[g] = 0;
        for (int g = b + 1; g <= bn; g++) g_goff[g] = e + 1;
    }
}

// ---------------- single-launch CSR scan (ticket + flag spin) ----------------
__global__ void __launch_bounds__(SCAN_TB) k_scanall() {
    __shared__ int sm[SCAN_TB];
    __shared__ int islast;
    int t = threadIdx.x;
    int b = blockIdx.x;
    int i = b * SCAN_TB + t;
    int c = (i < NN) ? g_cnt[i] : 0;
    // block-local inclusive scan
    sm[t] = c;
    __syncthreads();
    for (int off = 1; off < SCAN_TB; off <<= 1) {
        int u = (t >= off) ? sm[t - off] : 0;
        __syncthreads();
        sm[t] += u;
        __syncthreads();
    }
    int local_ex = sm[t] - c;
    int total = sm[SCAN_TB - 1];
    if (t == 0) {
        g_bsum[b] = total;
        __threadfence();
        islast = (atomicAdd(&g_tick, 1) == SCAN_NB - 1);
    }
    __syncthreads();
    if (islast) {
        // scan the 196 block sums (exclusive)
        int v = (t < SCAN_NB) ? g_bsum[t] : 0;
        __syncthreads();
        sm[t] = v;
        __syncthreads();
        for (int off = 1; off < SCAN_TB; off <<= 1) {
            int u = (t >= off) ? sm[t - off] : 0;
            __syncthreads();
            sm[t] += u;
            __syncthreads();
        }
        if (t < SCAN_NB) g_boff[t] = sm[t] - v;
        __threadfence();
        __syncthreads();
        if (t == 0) atomicExch(&g_flag, 1);
    }
    if (t == 0) {
        while (atomicAdd(&g_flag, 0) == 0) __nanosleep(100);
    }
    __syncthreads();
    __threadfence();
    int ex = local_ex + g_boff[b];
    if (i < NN) {
        g_ptr[i] = ex;
        g_dis[i] = rsqrtf((float)(c + 1));
        if (i == NN - 1) g_ptr[NN] = ex + c;
    }
}

__global__ void k_fill(const void* eidx) {
    int e = blockIdx.x * blockDim.x + threadIdx.x;
    if (e >= EE) return;
    int is64 = g_is64;
    int s = ld_idx(eidx, e, is64);
    int d = ld_idx(eidx, (long long)EE + e, is64);
    int pos = atomicAdd(&g_fill[d], 1);
    int slot = g_ptr[d] + pos;
    g_csr_src[slot] = s;
    g_csr_w[slot] = g_dis[s] * g_dis[d];
}

// ---------------- 3xTF32 GEMM, W pre-split, 128x128 tile, 512 thr ----------
// g_h16u[N,128](fp16) = f(X)[N,128] @ W[128,128]; f = id or BN+ReLU.
// Warps 4(M) x 4(N), warp tile 32x32 (2x4 m16n8k8), k-step 8.
#define XS_STRIDE 132
#define WS_STRIDE 136
#define GEMM_SMEM ((128 * XS_STRIDE + 2 * 128 * WS_STRIDE) * 4)

template <bool BN>
__global__ void __launch_bounds__(512) k_gemm_tc(const float* __restrict__ X,
                                                 const float* __restrict__ Wh,
                                                 const float* __restrict__ Wl) {
    extern __shared__ float smem[];
    float* Xs  = smem;                        // [128][XS_STRIDE] fp32
    float* Whs = Xs + 128 * XS_STRIDE;        // [128][WS_STRIDE] tf32-hi
    float* Wls = Whs + 128 * WS_STRIDE;       // [128][WS_STRIDE] tf32-lo
    int tid = threadIdx.x;
    int row0 = blockIdx.x * 128;

    // X tile 128x128 fp32 (fused BN+ReLU): 4096 f4 / 512 thr = 8 each
#pragma unroll
    for (int i = 0; i < 8; i++) {
        int q = i * 512 + tid;
        int r = q >> 5;
        int c = (q & 31) * 4;
        int gr = row0 + r;
        float4 v = make_float4(0.f, 0.f, 0.f, 0.f);
        if (gr < NN) v = *(const float4*)(X + (size_t)gr * 128 + c);
        if (BN) {
            v.x = fmaxf(g_bn_a[c + 0] * v.x + g_bn_b[c + 0], 0.f);
            v.y = fmaxf(g_bn_a[c + 1] * v.y + g_bn_b[c + 1], 0.f);
            v.z = fmaxf(g_bn_a[c + 2] * v.z + g_bn_b[c + 2], 0.f);
            v.w = fmaxf(g_bn_a[c + 3] * v.w + g_bn_b[c + 3], 0.f);
        }
        *(float4*)(Xs + r * XS_STRIDE + c) = v;
    }
    // W hi/lo tiles (pre-split, straight copies)
#pragma unroll
    for (int i = 0; i < 8; i++) {
        int q = i * 512 + tid;
        int r = q >> 5;
        int c = (q & 31) * 4;
        *(float4*)(Whs + r * WS_STRIDE + c) = *(const float4*)(Wh + (size_t)r * 128 + c);
        *(float4*)(Wls + r * WS_STRIDE + c) = *(const float4*)(Wl + (size_t)r * 128 + c);
    }
    __syncthreads();

    int wid = tid >> 5;
    int lane = tid & 31;
    int mwid = wid >> 2;   // 0..3
    int nwid = wid & 3;    // 0..3
    int g = lane >> 2;     // 0..7
    int tg = lane & 3;     // 0..3

    float acc[2][4][4];
#pragma unroll
    for (int mi = 0; mi < 2; mi++)
#pragma unroll
        for (int ni = 0; ni < 4; ni++)
#pragma unroll
            for (int j = 0; j < 4; j++) acc[mi][ni][j] = 0.f;

#define SPLIT(V, HI, LO)                                 \
    do {                                                 \
        HI = f2tf32(V);                                  \
        LO = f2tf32((V) - __uint_as_float(HI));          \
    } while (0)

#define MMA(A0, A1, A2, A3, B0, B1, C)                                        \
    asm volatile(                                                             \
        "mma.sync.aligned.m16n8k8.row.col.f32.tf32.tf32.f32 "                 \
        "{%0,%1,%2,%3}, {%4,%5,%6,%7}, {%8,%9}, {%0,%1,%2,%3};"               \
        : "+f"(C[0]), "+f"(C[1]), "+f"(C[2]), "+f"(C[3])                      \
        : "r"(A0), "r"(A1), "r"(A2), "r"(A3), "r"(B0), "r"(B1))

#pragma unroll
    for (int k0 = 0; k0 < 128; k0 += 8) {
        unsigned ah[2][4], al[2][4];
#pragma unroll
        for (int mi = 0; mi < 2; mi++) {
            int rb = mwid * 32 + mi * 16;
            int o0 = (rb + g) * XS_STRIDE + k0 + tg;
            int o1 = (rb + g + 8) * XS_STRIDE + k0 + tg;
            float v0 = Xs[o0], v1 = Xs[o1], v2 = Xs[o0 + 4], v3 = Xs[o1 + 4];
            SPLIT(v0, ah[mi][0], al[mi][0]);
            SPLIT(v1, ah[mi][1], al[mi][1]);
            SPLIT(v2, ah[mi][2], al[mi][2]);
            SPLIT(v3, ah[mi][3], al[mi][3]);
        }
        unsigned bh[4][2], bl[4][2];
#pragma unroll
        for (int ni = 0; ni < 4; ni++) {
            int cb = nwid * 32 + ni * 8;
            int o0 = (k0 + tg) * WS_STRIDE + cb + g;
            int o1 = (k0 + tg + 4) * WS_STRIDE + cb + g;
            bh[ni][0] = __float_as_uint(Whs[o0]);
            bh[ni][1] = __float_as_uint(Whs[o1]);
            bl[ni][0] = __float_as_uint(Wls[o0]);
            bl[ni][1] = __float_as_uint(Wls[o1]);
        }
#pragma unroll
        for (int mi = 0; mi < 2; mi++)
#pragma unroll
            for (int ni = 0; ni < 4; ni++) {
                MMA(ah[mi][0], ah[mi][1], ah[mi][2], ah[mi][3],
                    bh[ni][0], bh[ni][1], acc[mi][ni]);
                MMA(ah[mi][0], ah[mi][1], ah[mi][2], ah[mi][3],
                    bl[ni][0], bl[ni][1], acc[mi][ni]);
                MMA(al[mi][0], al[mi][1], al[mi][2], al[mi][3],
                    bh[ni][0], bh[ni][1], acc[mi][ni]);
            }
    }

    // epilogue: fp16 pairs
#pragma unroll
    for (int mi = 0; mi < 2; mi++) {
#pragma unroll
        for (int ni = 0; ni < 4; ni++) {
            int col = nwid * 32 + ni * 8 + tg * 2;
            int r1 = row0 + mwid * 32 + mi * 16 + g;
            int r2 = r1 + 8;
            if (r1 < NN) {
                __half2 h = __floats2half2_rn(acc[mi][ni][0], acc[mi][ni][1]);
                g_h16u[(size_t)r1 * 64 + (col >> 1)] = *(unsigned*)&h;
            }
            if (r2 < NN) {
                __half2 h = __floats2half2_rn(acc[mi][ni][2], acc[mi][ni][3]);
                g_h16u[(size_t)r2 * 64 + (col >> 1)] = *(unsigned*)&h;
            }
        }
    }
#undef MMA
#undef SPLIT
}

// ---------------- aggregation (fp16 gather) + fused BN partial stats --------
__global__ void __launch_bounds__(256) k_agg(const float* __restrict__ bias) {
    __shared__ float ps[8][HH];
    __shared__ float pq[8][HH];
    int w = threadIdx.x >> 5;
    int lane = threadIdx.x & 31;
    int d = blockIdx.x * 8 + w;   // NN = 6250*8 exact

    const uint2* Hv = (const uint2*)g_h16u;
    float sd = g_dis[d];
    float ws = sd * sd;
    uint2 u = Hv[(size_t)d * 32 + lane];
    float2 f0 = __half22float2(*(__half2*)&u.x);
    float2 f1 = __half22float2(*(__half2*)&u.y);
    float4 acc = make_float4(f0.x * ws, f0.y * ws, f1.x * ws, f1.y * ws);

    int beg = g_ptr[d], end = g_ptr[d + 1];
    int j = beg;
    for (; j + 4 <= end; j += 4) {
        int s0 = g_csr_src[j + 0], s1 = g_csr_src[j + 1];
        int s2 = g_csr_src[j + 2], s3 = g_csr_src[j + 3];
        float w0 = g_csr_w[j + 0], w1 = g_csr_w[j + 1];
        float w2 = g_csr_w[j + 2], w3 = g_csr_w[j + 3];
        uint2 u0 = Hv[(size_t)s0 * 32 + lane];
        uint2 u1 = Hv[(size_t)s1 * 32 + lane];
        uint2 u2 = Hv[(size_t)s2 * 32 + lane];
        uint2 u3 = Hv[(size_t)s3 * 32 + lane];
        float2 a, b;
        a = __half22float2(*(__half2*)&u0.x); b = __half22float2(*(__half2*)&u0.y);
        acc.x += a.x * w0; acc.y += a.y * w0; acc.z += b.x * w0; acc.w += b.y * w0;
        a = __half22float2(*(__half2*)&u1.x); b = __half22float2(*(__half2*)&u1.y);
        acc.x += a.x * w1; acc.y += a.y * w1; acc.z += b.x * w1; acc.w += b.y * w1;
        a = __half22float2(*(__half2*)&u2.x); b = __half22float2(*(__half2*)&u2.y);
        acc.x += a.x * w2; acc.y += a.y * w2; acc.z += b.x * w2; acc.w += b.y * w2;
        a = __half22float2(*(__half2*)&u3.x); b = __half22float2(*(__half2*)&u3.y);
        acc.x += a.x * w3; acc.y += a.y * w3; acc.z += b.x * w3; acc.w += b.y * w3;
    }
    for (; j < end; j++) {
        int s = g_csr_src[j];
        float wj = g_csr_w[j];
        uint2 us = Hv[(size_t)s * 32 + lane];
        float2 a = __half22float2(*(__half2*)&us.x);
        float2 b = __half22float2(*(__half2*)&us.y);
        acc.x += a.x * wj; acc.y += a.y * wj; acc.z += b.x * wj; acc.w += b.y * wj;
    }
    float4 b4 = ((const float4*)bias)[lane];
    acc.x += b4.x; acc.y += b4.y; acc.z += b4.z; acc.w += b4.w;
    ((float4*)(g_agg + (size_t)d * HH))[lane] = acc;

    // BN partial stats (deterministic fixed-order 8-way sum)
    int c0 = 4 * lane;
    ps[w][c0 + 0] = acc.x; ps[w][c0 + 1] = acc.y;
    ps[w][c0 + 2] = acc.z; ps[w][c0 + 3] = acc.w;
    pq[w][c0 + 0] = acc.x * acc.x; pq[w][c0 + 1] = acc.y * acc.y;
    pq[w][c0 + 2] = acc.z * acc.z; pq[w][c0 + 3] = acc.w * acc.w;
    __syncthreads();
    int t = threadIdx.x;
    if (t < HH) {
        float s = 0.f;
#pragma unroll
        for (int i = 0; i < 8; i++) s += ps[i][t];
        g_ps1[blockIdx.x * HH + t] = s;
    } else {
        int c = t - HH;
        float s = 0.f;
#pragma unroll
        for (int i = 0; i < 8; i++) s += pq[i][c];
        g_pq1[blockIdx.x * HH + c] = s;
    }
}

// ---------------- BN stats: one launch (mid + ticketed final) ----------------
#define ROWS_PER_STAT 49  /* 128*49 = 6272 >= 6250 */
__global__ void __launch_bounds__(256) k_stats(int which,
                                               const float* __restrict__ gam,
                                               const float* __restrict__ bet) {
    __shared__ int islast;
    int b = blockIdx.x;           // 128 blocks
    int t = threadIdx.x;          // 256 threads
    int c = t & (HH - 1);
    int isq = t >> 7;             // 0: sum, 1: sumsq
    const float* src = isq ? g_pq1 : g_ps1;
    float s = 0.f;
    int r0 = b * ROWS_PER_STAT;
    int r1 = r0 + ROWS_PER_STAT;
    if (r1 > AGG_NB) r1 = AGG_NB;
    for (int r = r0; r < r1; r++) s += src[r * HH + c];
    if (isq) g_midq[b * HH + c] = s;
    else     g_mids[b * HH + c] = s;
    __threadfence();
    if (t == 0) islast = (atomicAdd(&g_tick2[which], 1) == STAT_NB - 1);
    __syncthreads();
    if (!islast) return;
    if (t < HH) {
        float su = 0.f, q = 0.f;
        for (int b2 = 0; b2 < STAT_NB; b2++) {
            su += g_mids[b2 * HH + t];
            q  += g_midq[b2 * HH + t];
        }
        float m = su / (float)NN;
        float var = q / (float)NN - m * m;
        float a = gam[t] * rsqrtf(var + EPSBN);
        g_bn_a[t] = a;
        g_bn_b[t] = bet[t] - m * a;
    }
}

// ---------------- pool (BN3+ReLU fused) + FC1, one kernel ----------------
__global__ void __launch_bounds__(128) k_poolfc1(const float* __restrict__ Wf,
                                                 const float* __restrict__ bf) {
    __shared__ float pooled[HH];
    int gI = blockIdx.x;
    int c = threadIdx.x;          // 128 threads
    int beg = g_goff[gI], end = g_goff[gI + 1];
    float a = g_bn_a[c], b = g_bn_b[c];
    float acc = 0.f;
    for (int r = beg; r < end; r++) {
        float v = g_agg[(size_t)r * HH + c];
        acc += fmaxf(a * v + b, 0.f);
    }
    float cnt = (float)(end - beg);
    pooled[c] = acc / fmaxf(cnt, 1.f);
    __syncthreads();
    if (c < FC1) {
        float s = bf[c];
#pragma unroll 8
        for (int k = 0; k < HH; k++) s += pooled[k] * Wf[k * FC1 + c];
        g_z[gI * FC1 + c] = s;
    }
}

// ---------------- head: fc BN stats + fc2, one block ----------------
__global__ void __launch_bounds__(512) k_head(const float* __restrict__ gam,
                                              const float* __restrict__ bet,
                                              const float* __restrict__ W2f,
                                              const float* __restrict__ b2f,
                                              float* __restrict__ out) {
    __shared__ float fa[FC1], fb[FC1];
    int t = threadIdx.x;
    if (t < FC1) {
        float s = 0.f, q = 0.f;
#pragma unroll 4
        for (int r = 0; r < GG; r++) {
            float v = g_z[r * FC1 + t];
            s += v;
            q += v * v;
        }
        float m = s / (float)GG;
        float var = q / (float)GG - m * m;
        float a = gam[t] * rsqrtf(var + EPSBN);
        fa[t] = a;
        fb[t] = bet[t] - m * a;
    }
    __syncthreads();
    if (t < GG) {
        float s = b2f[0];
#pragma unroll 8
        for (int c = 0; c < FC1; c++) {
            float v = g_z[t * FC1 + c];
            v = fmaxf(fa[c] * v + fb[c], 0.f);
            s += v * W2f[c];
        }
        out[t] = s;
    }
}

// ---------------- launch ----------------
extern "C" void kernel_launch(void* const* d_in, const int* in_sizes, int n_in,
                              void* d_out, int out_size) {
    const float* x    = (const float*)d_in[0];
    const void*  eidx = d_in[1];
    const void*  batc = d_in[2];
    const float* W1 = (const float*)d_in[3];
    const float* b1 = (const float*)d_in[4];
    const float* g1 = (const float*)d_in[5];
    const float* be1 = (const float*)d_in[6];
    const float* W2 = (const float*)d_in[7];
    const float* b2 = (const float*)d_in[8];
    const float* g2 = (const float*)d_in[9];
    const float* be2 = (const float*)d_in[10];
    const float* W3 = (const float*)d_in[11];
    const float* b3 = (const float*)d_in[12];
    const float* g3 = (const float*)d_in[13];
    const float* be3 = (const float*)d_in[14];
    const float* fcW1 = (const float*)d_in[15];
    const float* fcb1 = (const float*)d_in[16];
    const float* fcg1 = (const float*)d_in[17];
    const float* fcbe1 = (const float*)d_in[18];
    const float* fcW2 = (const float*)d_in[19];
    const float* fcb2 = (const float*)d_in[20];
    float* out = (float*)d_out;

    float *pagg = nullptr, *pwh = nullptr, *pwl = nullptr;
    cudaGetSymbolAddress((void**)&pagg, g_agg);
    cudaGetSymbolAddress((void**)&pwh, g_wh);
    cudaGetSymbolAddress((void**)&pwl, g_wl);

    const int TB = 256;
    const int gemm_blocks = (NN + 127) / 128;
    static int smem_set = 0;
    if (!smem_set) {
        cudaFuncSetAttribute(k_gemm_tc<false>,
                             cudaFuncAttributeMaxDynamicSharedMemorySize, GEMM_SMEM);
        cudaFuncSetAttribute(k_gemm_tc<true>,
                             cudaFuncAttributeMaxDynamicSharedMemorySize, GEMM_SMEM);
        smem_set = 1;
    }

    k_pre1<<<SCAN_NB, TB>>>(eidx, W1, W2, W3);
    k_count<<<(EE + TB - 1) / TB, TB>>>(eidx, batc);
    k_scanall<<<SCAN_NB, SCAN_TB>>>();
    k_fill<<<(EE + TB - 1) / TB, TB>>>(eidx);

    // layer 1
    k_gemm_tc<false><<<gemm_blocks, 512, GEMM_SMEM>>>(x, pwh, pwl);
    k_agg<<<AGG_NB, TB>>>(b1);
    k_stats<<<STAT_NB, TB>>>(0, g1, be1);
    // layer 2
    k_gemm_tc<true><<<gemm_blocks, 512, GEMM_SMEM>>>(pagg, pwh + HH * HH, pwl + HH * HH);
    k_agg<<<AGG_NB, TB>>>(b2);
    k_stats<<<STAT_NB, TB>>>(1, g2, be2);
    // layer 3
    k_gemm_tc<true><<<gemm_blocks, 512, GEMM_SMEM>>>(pagg, pwh + 2 * HH * HH, pwl + 2 * HH * HH);
    k_agg<<<AGG_NB, TB>>>(b3);
    k_stats<<<STAT_NB, TB>>>(2, g3, be3);

    // pool+fc1, then head
    k_poolfc1<<<GG, 128>>>(fcW1, fcb1);
    k_head<<<1, 512>>>(fcg1, fcbe1, fcW2, fcb2, out);
}